// round 16
// baseline (speedup 1.0000x reference)
#include <cuda_runtime.h>
#include <cuda_bf16.h>
#include <math.h>
#include <stdint.h>

#define N_    64
#define C_    512
#define HW_   1024
#define K_    64
#define ALPHA_ 50.0f
#define EPS_  1e-12f

typedef unsigned short u16;

extern __shared__ char smem_u[];

// static scratch (split bf16 operand caches)
__device__ __align__(16) u16   g_whi[K_ * C_];
__device__ __align__(16) u16   g_wlo[K_ * C_];
__device__ __align__(16) u16   g_xhi[(size_t)N_ * C_ * HW_];
__device__ __align__(16) u16   g_xlo[(size_t)N_ * C_ * HW_];
__device__ __align__(16) u16   g_ahi[(size_t)N_ * K_ * HW_];
__device__ __align__(16) u16   g_alo[(size_t)N_ * K_ * HW_];
__device__ __align__(16) float g_asum_part[N_ * 32 * K_];
__device__ __align__(16) float g_ssq[N_ * K_ * 4];

// ---------------------------------------------------------------------------
__device__ __forceinline__ uint32_t s2u(const void* p) {
    uint32_t a;
    asm("{ .reg .u64 t; cvta.to.shared.u64 t, %1; cvt.u32.u64 %0, t; }" : "=r"(a) : "l"(p));
    return a;
}
__device__ __forceinline__ void mma16816(float* c, uint32_t a0, uint32_t a1,
                                         uint32_t a2, uint32_t a3,
                                         uint32_t b0, uint32_t b1) {
    asm volatile(
        "mma.sync.aligned.m16n8k16.row.col.f32.bf16.bf16.f32 "
        "{%0,%1,%2,%3}, {%4,%5,%6,%7}, {%8,%9}, {%0,%1,%2,%3};"
        : "+f"(c[0]), "+f"(c[1]), "+f"(c[2]), "+f"(c[3])
        : "r"(a0), "r"(a1), "r"(a2), "r"(a3), "r"(b0), "r"(b1));
}
__device__ __forceinline__ void ldsm_x4(uint32_t& r0, uint32_t& r1, uint32_t& r2,
                                        uint32_t& r3, uint32_t addr) {
    asm volatile("ldmatrix.sync.aligned.m8n8.x4.shared.b16 {%0,%1,%2,%3}, [%4];"
                 : "=r"(r0), "=r"(r1), "=r"(r2), "=r"(r3) : "r"(addr));
}
__device__ __forceinline__ void cpa(uint32_t dst, const u16* src) {
    asm volatile("cp.async.cg.shared.global [%0], [%1], 16;"
                 :: "r"(dst), "l"((size_t)__cvta_generic_to_global(src)) : "memory");
}
#define CP_COMMIT() asm volatile("cp.async.commit_group;" ::: "memory")
#define CP_WAIT1()  asm volatile("cp.async.wait_group 1;" ::: "memory")
#define CP_WAIT0()  asm volatile("cp.async.wait_group 0;" ::: "memory")

__device__ __forceinline__ void split1(float v, u16& h, u16& l) {
    __nv_bfloat16 bh = __float2bfloat16_rn(v);
    __nv_bfloat16 bl = __float2bfloat16_rn(v - __bfloat162float(bh));
    h = __bfloat16_as_ushort(bh);
    l = __bfloat16_as_ushort(bl);
}
__device__ __forceinline__ uint32_t pack2(u16 a, u16 b) {
    return (uint32_t)a | ((uint32_t)b << 16);
}

// ---------------------------------------------------------------------------
// k0: column-normalize W, emit split bf16 Wn^T [k][c]
// ---------------------------------------------------------------------------
__global__ void k0_kernel(const float* __restrict__ w) {
    int k = blockIdx.x, tid = threadIdx.x;
    __shared__ float red[256];
    float ss = 0.f;
    for (int c = tid; c < C_; c += 256) { float v = w[c * K_ + k]; ss += v * v; }
    red[tid] = ss; __syncthreads();
    for (int s = 128; s > 0; s >>= 1) { if (tid < s) red[tid] += red[tid + s]; __syncthreads(); }
    float inv = 1.f / fmaxf(sqrtf(red[0]), EPS_);
    for (int c = tid; c < C_; c += 256) {
        u16 h, l;
        split1(w[c * K_ + k] * inv, h, l);
        g_whi[k * C_ + c] = h;
        g_wlo[k * C_ + c] = l;
    }
}

// ---------------------------------------------------------------------------
// kF: fused norm + transpose + split-emit + GEMM1 + softmax.
// Block = (n, 32 hw), full C. Writes feat f32, g_xhi/g_xlo, sa, g_ahi/g_alo,
// asum partials.
// smem: xs[512][33] f32 @0 (67584) | inv @67584 | part @67712 | bias @68736 |
//       B stages @69120: 2 x (BH 64*72*2 + BL) = 36864 ; ls aliases stage0
// ---------------------------------------------------------------------------
#define F_INV   67584
#define F_PART  67712
#define F_BIAS  68736
#define F_BOFF  69120
#define F_SMEM  105984

__global__ void __launch_bounds__(256, 2)
kF(const float* __restrict__ x, const float* __restrict__ bias,
   float* __restrict__ feat, float* __restrict__ sa) {
    char* sm = smem_u;
    uint32_t ubase = s2u(sm);
    float* xs   = (float*)sm;
    float* inv  = (float*)(sm + F_INV);
    float* part = (float*)(sm + F_PART);
    float* bsm  = (float*)(sm + F_BIAS);
    float* ls   = (float*)(sm + F_BOFF);            // post-GEMM alias (8576B)
    float* red2 = (float*)(sm + F_BOFF + 9216);     // post-GEMM alias (1KB)

    int tid = threadIdx.x, wid = tid >> 5, lane = tid & 31;
    int g = lane >> 2, t = lane & 3;
    int n = blockIdx.x >> 5, blk = blockIdx.x & 31;
    int hw0 = blk << 5;
    int mh = wid >> 2;                 // m-half 0/1 (hw rows mh*16..+15)
    int kg = wid & 3;                  // k-group (clusters kg*16..+15)
    int r0 = mh * 16 + g, r1 = r0 + 8;
    int brow = ((lane & 7) + ((lane >> 4) << 3)) * 72 + (((lane >> 3) & 1) << 3)
             + kg * 16 * 72;

    auto issueW = [&](int stage, int chunk) {
        uint32_t sb = ubase + F_BOFF + stage * 18432;
        int cc = chunk << 6;
        #pragma unroll
        for (int i = 0; i < 2; i++) {
            int idx = tid + (i << 8);
            int row = idx >> 3, q = idx & 7;
            cpa(sb + row * 144 + q * 16, g_whi + row * C_ + cc + q * 8);
            cpa(sb + 9216 + row * 144 + q * 16, g_wlo + row * C_ + cc + q * 8);
        }
    };

    issueW(0, 0);
    CP_COMMIT();
    if (tid < K_) bsm[tid] = bias[tid];

    // --- load x [512c][32hw] ---
    const float* xp = x + (size_t)n * C_ * HW_ + hw0;
    #pragma unroll
    for (int it = 0; it < 16; it++) {
        int idx = tid + it * 256;
        int c = idx >> 3, q = idx & 7;
        float4 v = *(const float4*)(xp + (size_t)c * HW_ + 4 * q);
        xs[c * 33 + 4 * q    ] = v.x;
        xs[c * 33 + 4 * q + 1] = v.y;
        xs[c * 33 + 4 * q + 2] = v.z;
        xs[c * 33 + 4 * q + 3] = v.w;
    }
    __syncthreads();
    {
        int j = tid & 31, tt = tid >> 5;
        float ss = 0.f;
        #pragma unroll 8
        for (int c = tt; c < C_; c += 8) { float v = xs[c * 33 + j]; ss += v * v; }
        part[tid] = ss;
    }
    __syncthreads();
    if (tid < 32) {
        float ss = 0.f;
        #pragma unroll
        for (int tt = 0; tt < 8; tt++) ss += part[tt * 32 + tid];
        inv[tid] = 1.f / fmaxf(sqrtf(ss), EPS_);
    }
    __syncthreads();

    // --- feat f32 [hw][c] ---
    float* fp = feat + ((size_t)n * HW_ + hw0) * C_;
    #pragma unroll
    for (int it = 0; it < 16; it++) {
        int idx = tid + it * 256;
        int j = idx >> 7, c4 = (idx & 127) * 4;
        float iv = inv[j];
        float4 v;
        v.x = xs[(c4 + 0) * 33 + j] * iv;
        v.y = xs[(c4 + 1) * 33 + j] * iv;
        v.z = xs[(c4 + 2) * 33 + j] * iv;
        v.w = xs[(c4 + 3) * 33 + j] * iv;
        *(float4*)(fp + (size_t)j * C_ + c4) = v;
    }
    // --- x split emit [c][hw] (for kG2) ---
    {
        u16* xh = g_xhi + (size_t)n * C_ * HW_ + hw0;
        u16* xl = g_xlo + (size_t)n * C_ * HW_ + hw0;
        #pragma unroll
        for (int it = 0; it < 32; it++) {
            int idx = tid + it * 256;
            int c = idx >> 4, jp = (idx & 15) * 2;
            float v0 = xs[c * 33 + jp    ] * inv[jp    ];
            float v1 = xs[c * 33 + jp + 1] * inv[jp + 1];
            u16 h0, l0, h1, l1;
            split1(v0, h0, l0);
            split1(v1, h1, l1);
            *(uint32_t*)(xh + (size_t)c * HW_ + jp) = pack2(h0, h1);
            *(uint32_t*)(xl + (size_t)c * HW_ + jp) = pack2(l0, l1);
        }
    }

    // --- GEMM1: logits[32hw][64k], A from registers (split from xs), B staged W ---
    float inv0 = inv[r0], inv1 = inv[r1];
    float acc[2][4] = {};
    #pragma unroll 1
    for (int cc = 0; cc < 8; cc++) {
        if (cc < 7) { issueW((cc + 1) & 1, cc + 1); CP_COMMIT(); CP_WAIT1(); }
        else        { CP_WAIT0(); }
        __syncthreads();
        uint32_t uBH = ubase + F_BOFF + (cc & 1) * 18432;
        uint32_t uBL = uBH + 9216;
        #pragma unroll
        for (int kk = 0; kk < 64; kk += 16) {
            int c0 = (cc << 6) + kk + 2 * t;
            float x00 = xs[(c0    ) * 33 + r0] * inv0;
            float x01 = xs[(c0 + 1) * 33 + r0] * inv0;
            float x10 = xs[(c0    ) * 33 + r1] * inv1;
            float x11 = xs[(c0 + 1) * 33 + r1] * inv1;
            float x02 = xs[(c0 + 8) * 33 + r0] * inv0;
            float x03 = xs[(c0 + 9) * 33 + r0] * inv0;
            float x12 = xs[(c0 + 8) * 33 + r1] * inv1;
            float x13 = xs[(c0 + 9) * 33 + r1] * inv1;
            u16 h00,l00,h01,l01,h10,l10,h11,l11,h02,l02,h03,l03,h12,l12,h13,l13;
            split1(x00,h00,l00); split1(x01,h01,l01);
            split1(x10,h10,l10); split1(x11,h11,l11);
            split1(x02,h02,l02); split1(x03,h03,l03);
            split1(x12,h12,l12); split1(x13,h13,l13);
            uint32_t ah0 = pack2(h00,h01), ah1 = pack2(h10,h11);
            uint32_t ah2 = pack2(h02,h03), ah3 = pack2(h12,h13);
            uint32_t al0 = pack2(l00,l01), al1 = pack2(l10,l11);
            uint32_t al2 = pack2(l02,l03), al3 = pack2(l12,l13);
            uint32_t b0, b1, b2, b3;
            ldsm_x4(b0, b1, b2, b3, uBH + (uint32_t)(brow + kk) * 2);
            mma16816(acc[0], ah0, ah1, ah2, ah3, b0, b1);
            mma16816(acc[1], ah0, ah1, ah2, ah3, b2, b3);
            mma16816(acc[0], al0, al1, al2, al3, b0, b1);
            mma16816(acc[1], al0, al1, al2, al3, b2, b3);
            uint32_t d0, d1, d2, d3;
            ldsm_x4(d0, d1, d2, d3, uBL + (uint32_t)(brow + kk) * 2);
            mma16816(acc[0], ah0, ah1, ah2, ah3, d0, d1);
            mma16816(acc[1], ah0, ah1, ah2, ah3, d2, d3);
        }
        __syncthreads();
    }

    // dump logits to ls[32hw][67]
    #pragma unroll
    for (int nb = 0; nb < 2; nb++) {
        int col = kg * 16 + nb * 8 + 2 * t;
        ls[(r0) * 67 + col    ] = acc[nb][0];
        ls[(r0) * 67 + col + 1] = acc[nb][1];
        ls[(r1) * 67 + col    ] = acc[nb][2];
        ls[(r1) * 67 + col + 1] = acc[nb][3];
    }
    __syncthreads();
    // sa_logits out
    {
        float* sp = sa + (size_t)n * K_ * HW_ + hw0;
        #pragma unroll
        for (int it = 0; it < 8; it++) {
            int idx = tid + it * 256;
            int k = idx >> 5, j = idx & 31;
            sp[(size_t)k * HW_ + j] = ls[j * 67 + k];
        }
    }
    __syncthreads();
    // softmax per hw column (tid<32)
    if (tid < 32) {
        int j = tid;
        float f[64];
        float m = -1e30f;
        #pragma unroll
        for (int k = 0; k < K_; k++) {
            float v = (ls[j * 67 + k] + bsm[k]) * ALPHA_;
            f[k] = v;
            m = fmaxf(m, v);
        }
        float s = 0.f;
        #pragma unroll
        for (int k = 0; k < K_; k++) { float e = __expf(f[k] - m); f[k] = e; s += e; }
        float is = 1.f / s;
        #pragma unroll
        for (int k = 0; k < K_; k++) ls[j * 67 + k] = f[k] * is;
    }
    __syncthreads();
    // a-splits + asum partials
    {
        u16* ah = g_ahi + (size_t)n * K_ * HW_ + hw0;
        u16* al = g_alo + (size_t)n * K_ * HW_ + hw0;
        int k = tid >> 2, jq = tid & 3;
        u16 h[8], l[8];
        float s = 0.f;
        #pragma unroll
        for (int i = 0; i < 8; i++) {
            float a = ls[(jq * 8 + i) * 67 + k];
            s += a;
            split1(a, h[i], l[i]);
        }
        uint4 hp = make_uint4(pack2(h[0],h[1]), pack2(h[2],h[3]),
                              pack2(h[4],h[5]), pack2(h[6],h[7]));
        uint4 lp = make_uint4(pack2(l[0],l[1]), pack2(l[2],l[3]),
                              pack2(l[4],l[5]), pack2(l[6],l[7]));
        *(uint4*)(ah + (size_t)k * HW_ + jq * 8) = hp;
        *(uint4*)(al + (size_t)k * HW_ + jq * 8) = lp;
        red2[tid] = s;
    }
    __syncthreads();
    if (tid < K_) {
        float s = (red2[tid * 4] + red2[tid * 4 + 1]) + (red2[tid * 4 + 2] + red2[tid * 4 + 3]);
        g_asum_part[(n * 32 + blk) * K_ + tid] = s;
    }
}

// ---------------------------------------------------------------------------
// kG2: D[128c][64k] = (x*inv) @ a^T, contraction h. Pure-copy cp.async staging.
// ---------------------------------------------------------------------------
#define S2STG   55296
#define S2_AL   18432
#define S2_BH   36864
#define S2_BL   46080
#define G2_ASUM 110592
#define G2_SMEM 110848

__global__ void __launch_bounds__(256, 2)
kG2(const float* __restrict__ w, float* __restrict__ vlad) {
    char* sm = smem_u;
    uint32_t ubase = s2u(sm);
    float* ls   = (float*)sm;
    float* asum = (float*)(sm + G2_ASUM);

    int tid = threadIdx.x, wid = tid >> 5, lane = tid & 31;
    int g = lane >> 2, t = lane & 3;
    int row0 = wid * 16;
    int n = blockIdx.x >> 2, ct = blockIdx.x & 3;
    int c0b = ct << 7;

    int arow = (row0 + (lane & 15)) * 72 + ((lane >> 4) << 3);
    int brow = ((lane & 7) + ((lane >> 4) << 3)) * 72 + (((lane >> 3) & 1) << 3);

    if (tid < K_) {
        const float* pp = g_asum_part + n * 32 * K_ + tid;
        float s = 0.f;
        #pragma unroll
        for (int b = 0; b < 32; b++) s += pp[b * K_];
        asum[tid] = s;
    }

    float acc[8][4];
    #pragma unroll
    for (int nb = 0; nb < 8; nb++)
        #pragma unroll
        for (int i = 0; i < 4; i++) acc[nb][i] = 0.f;

    auto issue = [&](int stage, int tile) {
        uint32_t sb = ubase + stage * S2STG;
        int h0 = tile << 6;
        #pragma unroll
        for (int i = 0; i < 4; i++) {
            int idx = tid + (i << 8);
            int row = idx >> 3, q = idx & 7;
            size_t so = (size_t)(n * C_ + c0b + row) * HW_ + h0 + q * 8;
            cpa(sb + row * 144 + q * 16, g_xhi + so);
            cpa(sb + S2_AL + row * 144 + q * 16, g_xlo + so);
        }
        #pragma unroll
        for (int i = 0; i < 2; i++) {
            int idx = tid + (i << 8);
            int row = idx >> 3, q = idx & 7;
            size_t so = (size_t)(n * K_ + row) * HW_ + h0 + q * 8;
            cpa(sb + S2_BH + row * 144 + q * 16, g_ahi + so);
            cpa(sb + S2_BL + row * 144 + q * 16, g_alo + so);
        }
    };

    issue(0, 0);
    CP_COMMIT();
    #pragma unroll 1
    for (int it = 0; it < 16; it++) {
        if (it < 15) { issue((it + 1) & 1, it + 1); CP_COMMIT(); CP_WAIT1(); }
        else         { CP_WAIT0(); }
        __syncthreads();
        uint32_t uAH = ubase + (it & 1) * S2STG;
        uint32_t uAL = uAH + S2_AL, uBH = uAH + S2_BH, uBL = uAH + S2_BL;
        #pragma unroll
        for (int kk = 0; kk < 64; kk += 16) {
            uint32_t ah0, ah1, ah2, ah3, al0, al1, al2, al3;
            ldsm_x4(ah0, ah1, ah2, ah3, uAH + (uint32_t)(arow + kk) * 2);
            ldsm_x4(al0, al1, al2, al3, uAL + (uint32_t)(arow + kk) * 2);
            #pragma unroll
            for (int nb2 = 0; nb2 < 4; nb2++) {
                uint32_t off = (uint32_t)(nb2 * 16 * 72 + brow + kk) * 2;
                uint32_t b0, b1, b2, b3;
                ldsm_x4(b0, b1, b2, b3, uBH + off);
                mma16816(acc[2 * nb2    ], ah0, ah1, ah2, ah3, b0, b1);
                mma16816(acc[2 * nb2 + 1], ah0, ah1, ah2, ah3, b2, b3);
                mma16816(acc[2 * nb2    ], al0, al1, al2, al3, b0, b1);
                mma16816(acc[2 * nb2 + 1], al0, al1, al2, al3, b2, b3);
                uint32_t c0, c1, c2, c3;
                ldsm_x4(c0, c1, c2, c3, uBL + off);
                mma16816(acc[2 * nb2    ], ah0, ah1, ah2, ah3, c0, c1);
                mma16816(acc[2 * nb2 + 1], ah0, ah1, ah2, ah3, c2, c3);
            }
        }
        __syncthreads();
    }

    #pragma unroll
    for (int nb = 0; nb < 8; nb++) {
        int col = nb * 8 + 2 * t;
        ls[(row0 + g    ) * 67 + col    ] = acc[nb][0];
        ls[(row0 + g    ) * 67 + col + 1] = acc[nb][1];
        ls[(row0 + g + 8) * 67 + col    ] = acc[nb][2];
        ls[(row0 + g + 8) * 67 + col + 1] = acc[nb][3];
    }
    __syncthreads();
    if (tid < 128) {
        int c = c0b + tid;
        float f[64];
        #pragma unroll
        for (int i = 0; i < 16; i++) {
            float4 wv = *(const float4*)(w + (size_t)c * K_ + 4 * i);
            f[4 * i    ] = ls[tid * 67 + 4 * i    ] - asum[4 * i    ] * wv.x;
            f[4 * i + 1] = ls[tid * 67 + 4 * i + 1] - asum[4 * i + 1] * wv.y;
            f[4 * i + 2] = ls[tid * 67 + 4 * i + 2] - asum[4 * i + 2] * wv.z;
            f[4 * i + 3] = ls[tid * 67 + 4 * i + 3] - asum[4 * i + 3] * wv.w;
        }
        float* vp = vlad + (size_t)n * K_ * C_ + c;
        #pragma unroll
        for (int k = 0; k < K_; k++) {
            vp[(size_t)k * C_] = f[k];
            ls[tid * 67 + k] = f[k];
        }
    }
    __syncthreads();
    if (tid < K_) {
        float s = 0.f;
        #pragma unroll 4
        for (int c = 0; c < 128; c++) { float v = ls[c * 67 + tid]; s += v * v; }
        g_ssq[(n * K_ + tid) * 4 + ct] = s;
    }
}

// ---------------------------------------------------------------------------
// k3: row L2 norm of vlad
// ---------------------------------------------------------------------------
__global__ void k3_kernel(float* __restrict__ vlad) {
    int row = blockIdx.x;
    const float* sp = g_ssq + row * 4;
    float ssq = (sp[0] + sp[1]) + (sp[2] + sp[3]);
    float iv = 1.f / fmaxf(sqrtf(ssq), EPS_);
    float4* vp = (float4*)(vlad + (size_t)row * C_);
    float4 v = vp[threadIdx.x];
    v.x *= iv; v.y *= iv; v.z *= iv; v.w *= iv;
    vp[threadIdx.x] = v;
}

// ---------------------------------------------------------------------------
extern "C" void kernel_launch(void* const* d_in, const int* in_sizes, int n_in,
                              void* d_out, int out_size) {
    const float* x    = (const float*)d_in[0];   // [64,512,32,32]
    const float* w    = (const float*)d_in[1];   // [512,64]
    const float* bias = (const float*)d_in[2];   // [64]
    float* out  = (float*)d_out;
    float* vlad = out;                                    // [64, 64*512]
    float* sa   = out + (size_t)N_ * K_ * C_;             // [64, 64, 1024]
    float* feat = sa  + (size_t)N_ * K_ * HW_;            // [64, 1024, 512]

    cudaFuncSetAttribute(kF,  cudaFuncAttributeMaxDynamicSharedMemorySize, F_SMEM);
    cudaFuncSetAttribute(kG2, cudaFuncAttributeMaxDynamicSharedMemorySize, G2_SMEM);

    k0_kernel<<<K_, 256>>>(w);
    kF<<<N_ * 32, 256, F_SMEM>>>(x, bias, feat, sa);
    kG2<<<N_ * 4, 256, G2_SMEM>>>(w, vlad);
    k3_kernel<<<N_ * K_, 128>>>(vlad);
}